// round 1
// baseline (speedup 1.0000x reference)
#include <cuda_runtime.h>
#include <cstdint>

// ---------------------------------------------------------------------------
// GumbelVectorQuantizer: logits GEMM + gumbel argmax gather + perplexities
// Shapes: x[32768,768], W[768,640], b[640], codebook[640,128], noise[32768,640]
// out: [32768*256] floats, then code_perplexity, prob_perplexity
// ---------------------------------------------------------------------------

#define BT     32768
#define DD     768
#define GK     640
#define KCODE  320
#define VDIM   128

// scratch (device globals: allocation-free rule)
__device__ float g_logits[(size_t)BT * GK];   // 83.9 MB
__device__ float g_prob[GK];
__device__ int   g_cnt[GK];

// ---------------- fast math (FMA-pipe, ~1 ulp, cephes) ----------------------
__device__ __forceinline__ float flog(float x) {
    int xi = __float_as_int(x);
    float e = (float)(((xi >> 23) & 0xFF) - 126);
    float m = __int_as_float((xi & 0x007FFFFF) | 0x3F000000);  // [0.5,1)
    if (m < 0.70710678f) { m += m; e -= 1.0f; }
    float f = m - 1.0f;
    float z = f * f;
    float p = 7.0376836292E-2f;
    p = fmaf(p, f, -1.1514610310E-1f);
    p = fmaf(p, f,  1.1676998740E-1f);
    p = fmaf(p, f, -1.2420140846E-1f);
    p = fmaf(p, f,  1.4249322787E-1f);
    p = fmaf(p, f, -1.6668057665E-1f);
    p = fmaf(p, f,  2.0000714765E-1f);
    p = fmaf(p, f, -2.4999993993E-1f);
    p = fmaf(p, f,  3.3333331174E-1f);
    float y = p * f * z;
    y = fmaf(e, -2.12194440e-4f, y);
    y = fmaf(-0.5f, z, y);
    float r = f + y;
    r = fmaf(e, 0.693359375f, r);
    return r;
}

__device__ __forceinline__ float fexp(float x) {
    x = fmaxf(x, -87.0f);                 // inputs are <= 0 (softmax shifted)
    float t = x * 1.4426950408889634f;
    int   i = __float2int_rn(t);
    float fi = (float)i;
    float f = fmaf(fi, -0.693359375f, x);
    f = fmaf(fi, 2.12194440e-4f, f);
    float p = 1.9875691500E-4f;
    p = fmaf(p, f, 1.3981999507E-3f);
    p = fmaf(p, f, 8.3334519073E-3f);
    p = fmaf(p, f, 4.1665795894E-2f);
    p = fmaf(p, f, 1.6666665459E-1f);
    p = fmaf(p, f, 5.0000001201E-1f);
    float r = fmaf(p, f * f, f) + 1.0f;
    return r * __int_as_float((i + 127) << 23);
}

// ---------------- kernel 0: zero accumulators --------------------------------
__global__ void zero_kernel() {
    int t = blockIdx.x * blockDim.x + threadIdx.x;
    if (t < GK) { g_prob[t] = 0.0f; g_cnt[t] = 0; }
}

// ---------------- kernel 1: fp32 GEMM logits = x@W + b -----------------------
// Tile 128x128, BK=16, 256 threads, 8x8 per thread.
// Accumulation strictly sequential in ascending k (single FMA chain per output)
// to track the reference's CPU-gebp accumulation order as closely as possible.
__global__ __launch_bounds__(256, 2)
void gemm_kernel(const float* __restrict__ X, const float* __restrict__ W,
                 const float* __restrict__ bias) {
    __shared__ float As[16][132];   // transposed A tile, padded
    __shared__ float Bs[16][128];

    const int tid = threadIdx.x;
    const int tx = tid & 15;
    const int ty = tid >> 4;
    const int bm = blockIdx.y;      // 0..255
    const int bn = blockIdx.x;      // 0..4

    const float* Xb = X + (size_t)bm * 128 * DD;
    const float* Wb = W + bn * 128;

    float acc[8][8];
#pragma unroll
    for (int i = 0; i < 8; i++)
#pragma unroll
        for (int j = 0; j < 8; j++) acc[i][j] = 0.0f;

    const int a_row0 = tid >> 2;        // 0..63
    const int a_c4   = (tid & 3) * 4;   // 0,4,8,12
    const int b_row0 = tid >> 5;        // 0..7
    const int b_c    = (tid & 31) * 4;  // 0..124

    for (int k0 = 0; k0 < DD; k0 += 16) {
#pragma unroll
        for (int l = 0; l < 2; l++) {
            int row = a_row0 + l * 64;
            float4 v = *(const float4*)(Xb + (size_t)row * DD + k0 + a_c4);
            As[a_c4 + 0][row] = v.x;
            As[a_c4 + 1][row] = v.y;
            As[a_c4 + 2][row] = v.z;
            As[a_c4 + 3][row] = v.w;
        }
#pragma unroll
        for (int l = 0; l < 2; l++) {
            int row = b_row0 + l * 8;
            *(float4*)(&Bs[row][b_c]) =
                *(const float4*)(Wb + (size_t)(k0 + row) * GK + b_c);
        }
        __syncthreads();
#pragma unroll
        for (int kk = 0; kk < 16; kk++) {
            float a[8], bb[8];
#pragma unroll
            for (int i = 0; i < 8; i++) a[i] = As[kk][ty * 8 + i];
            float4 bv0 = *(const float4*)(&Bs[kk][tx * 8]);
            float4 bv1 = *(const float4*)(&Bs[kk][tx * 8 + 4]);
            bb[0] = bv0.x; bb[1] = bv0.y; bb[2] = bv0.z; bb[3] = bv0.w;
            bb[4] = bv1.x; bb[5] = bv1.y; bb[6] = bv1.z; bb[7] = bv1.w;
#pragma unroll
            for (int i = 0; i < 8; i++)
#pragma unroll
                for (int j = 0; j < 8; j++)
                    acc[i][j] = fmaf(a[i], bb[j], acc[i][j]);
        }
        __syncthreads();
    }

    float bvv[8];
#pragma unroll
    for (int j = 0; j < 8; j++) bvv[j] = bias[bn * 128 + tx * 8 + j];
#pragma unroll
    for (int i = 0; i < 8; i++) {
        size_t m = (size_t)bm * 128 + ty * 8 + i;
        float* crow = g_logits + m * GK + bn * 128 + tx * 8;
        float4 o0 = make_float4(acc[i][0] + bvv[0], acc[i][1] + bvv[1],
                                acc[i][2] + bvv[2], acc[i][3] + bvv[3]);
        float4 o1 = make_float4(acc[i][4] + bvv[4], acc[i][5] + bvv[5],
                                acc[i][6] + bvv[6], acc[i][7] + bvv[7]);
        *(float4*)crow       = o0;
        *(float4*)(crow + 4) = o1;
    }
}

// ---------------- kernel 2: fused epilogue -----------------------------------
// One warp per (row, group) pair; 16 pairs per warp; 8 warps per block.
// pair = 2*r + g, so logits row offset = pair*320, noise offset = pair*320.
__global__ __launch_bounds__(256)
void epilogue_kernel(const float* __restrict__ noise,
                     const float* __restrict__ cb,
                     float* __restrict__ out) {
    __shared__ float s_prob[GK];
    __shared__ int   s_cnt[GK];
    const int tid = threadIdx.x;
    for (int i = tid; i < GK; i += 256) { s_prob[i] = 0.0f; s_cnt[i] = 0; }
    __syncthreads();

    const int lane = tid & 31;
    const int warp = tid >> 5;
    const int pair0 = (blockIdx.x * 8 + warp) * 16;

    for (int pp = 0; pp < 16; pp++) {
        const int pair = pair0 + pp;
        const int r = pair >> 1;
        const int g = pair & 1;
        const float* lrow = g_logits + (size_t)pair * KCODE;
        const float* nrow = noise    + (size_t)pair * KCODE;

        float l[10], gl[10];
#pragma unroll
        for (int j = 0; j < 10; j++) {
            const int k = lane + 32 * j;
            const float lv = lrow[k];
            float u = nrow[k];
            u = fmaf(u, 0.999998f, 1e-6f);          // u*(1-2e-6)+1e-6
            const float gum = -flog(-flog(u));      // standard Gumbel
            l[j]  = lv;
            gl[j] = lv + gum;                       // argmax invariant to /tau
        }

        // hard argmax (for code perplexity counts); ties -> smallest k
        float M = l[0]; int I = lane;
#pragma unroll
        for (int j = 1; j < 10; j++)
            if (l[j] > M) { M = l[j]; I = lane + 32 * j; }
#pragma unroll
        for (int off = 16; off; off >>= 1) {
            float ov = __shfl_down_sync(0xffffffffu, M, off);
            int   oi = __shfl_down_sync(0xffffffffu, I, off);
            if (ov > M || (ov == M && oi < I)) { M = ov; I = oi; }
        }
        M = __shfl_sync(0xffffffffu, M, 0);
        I = __shfl_sync(0xffffffffu, I, 0);

        // gumbel argmax (selects the codebook row for the output)
        float GM = gl[0]; int GI = lane;
#pragma unroll
        for (int j = 1; j < 10; j++)
            if (gl[j] > GM) { GM = gl[j]; GI = lane + 32 * j; }
#pragma unroll
        for (int off = 16; off; off >>= 1) {
            float ov = __shfl_down_sync(0xffffffffu, GM, off);
            int   oi = __shfl_down_sync(0xffffffffu, GI, off);
            if (ov > GM || (ov == GM && oi < GI)) { GM = ov; GI = oi; }
        }
        GI = __shfl_sync(0xffffffffu, GI, 0);

        // softmax(logits) accumulation for prob perplexity
        float e[10];
        float s = 0.0f;
#pragma unroll
        for (int j = 0; j < 10; j++) { e[j] = fexp(l[j] - M); s += e[j]; }
#pragma unroll
        for (int off = 16; off; off >>= 1)
            s += __shfl_xor_sync(0xffffffffu, s, off);
        const float inv = 1.0f / s;

        const int kb = g * KCODE;
#pragma unroll
        for (int j = 0; j < 10; j++)
            atomicAdd(&s_prob[kb + lane + 32 * j], e[j] * inv);
        if (lane == 0) atomicAdd(&s_cnt[kb + I], 1);

        // output gather: out[r, g*128 : g*128+128] = codebook[g*320 + GI, :]
        const float4* src = (const float4*)(cb + ((size_t)kb + GI) * VDIM);
        float4*       dst = (float4*)(out + (size_t)r * 256 + g * VDIM);
        dst[lane] = src[lane];
    }

    __syncthreads();
    for (int i = tid; i < GK; i += 256) {
        atomicAdd(&g_prob[i], s_prob[i]);
        atomicAdd(&g_cnt[i],  s_cnt[i]);
    }
}

// ---------------- kernel 3: perplexity scalars --------------------------------
__global__ void finalize_kernel(float* __restrict__ out, int scalar_base) {
    __shared__ float sh[GK], sp[GK];
    const int t = threadIdx.x;
    if (t < GK) {
        float hp = (float)g_cnt[t] * (1.0f / (float)BT);
        float ap = g_prob[t]       * (1.0f / (float)BT);
        sh[t] = hp * logf(hp + 1e-7f);
        sp[t] = ap * logf(ap + 1e-7f);
    }
    __syncthreads();
    if (t == 0) {
        float h0 = 0.f, h1 = 0.f, p0 = 0.f, p1 = 0.f;
        for (int k = 0; k < KCODE; k++) {
            h0 += sh[k]; h1 += sh[KCODE + k];
            p0 += sp[k]; p1 += sp[KCODE + k];
        }
        out[scalar_base]     = expf(-h0) + expf(-h1);  // code_perplexity
        out[scalar_base + 1] = expf(-p0) + expf(-p1);  // prob_perplexity
    }
}

// ---------------- launch -------------------------------------------------------
extern "C" void kernel_launch(void* const* d_in, const int* in_sizes, int n_in,
                              void* d_out, int out_size) {
    const float* x     = (const float*)d_in[0];  // [32768,768]
    const float* W     = (const float*)d_in[1];  // [768,640]
    const float* bias  = (const float*)d_in[2];  // [640]
    const float* cb    = (const float*)d_in[3];  // [640,128]
    const float* noise = (const float*)d_in[4];  // [32768,640]
    float* out = (float*)d_out;

    zero_kernel<<<3, 256>>>();
    dim3 grid(5, 256);                 // N/128 = 5, M/128 = 256
    gemm_kernel<<<grid, 256>>>(x, W, bias);
    epilogue_kernel<<<512, 256>>>(noise, cb, out);  // 512*8 warps * 16 pairs = 65536
    finalize_kernel<<<1, GK>>>(out, out_size - 2);
}

// round 3
// speedup vs baseline: 1.3546x; 1.3546x over previous
#include <cuda_runtime.h>
#include <cuda_bf16.h>
#include <cstdint>

// ---------------------------------------------------------------------------
// GumbelVectorQuantizer on GB300 (sm_103 baseline ISA path):
//   logits = x@W + b via HMMA (mma.sync m16n8k16 bf16) 2-split emulated fp32
//   epilogue: gumbel argmax gather + perplexity accumulators + near-tie record
//   fixup:    exact sequential-FMA recompute of near-tie rows (bit-tracks ref)
// Shapes: x[32768,768], W[768,640], b[640], codebook[640,128], noise[32768,640]
// ---------------------------------------------------------------------------

#define BT     32768
#define DD     768
#define GK     640
#define KC     320
#define VDIM   128
#define NCHUNK 48          // K chunks of 16
#define THETA  4e-3f       // near-tie threshold (>13 sigma of split error)
#define MAXFIX 65536

// ---------------- device scratch (allocation-free rule) ----------------------
__device__ float g_logits[(size_t)BT * GK];                    // 83.9 MB
__device__ float g_prob[GK];
__device__ int   g_cnt[GK];
__device__ __align__(16) __nv_bfloat16 g_wt[2][(size_t)GK * DD];  // W^T hi/mid
__device__ int   g_fix_cnt;
__device__ int2  g_fix[MAXFIX];   // {pair, approx hard-argmax I}

// ---------------- fast math (FMA-pipe, ~1 ulp) -------------------------------
__device__ __forceinline__ float flog(float x) {
    int xi = __float_as_int(x);
    float e = (float)(((xi >> 23) & 0xFF) - 126);
    float m = __int_as_float((xi & 0x007FFFFF) | 0x3F000000);
    if (m < 0.70710678f) { m += m; e -= 1.0f; }
    float f = m - 1.0f;
    float z = f * f;
    float p = 7.0376836292E-2f;
    p = fmaf(p, f, -1.1514610310E-1f);
    p = fmaf(p, f,  1.1676998740E-1f);
    p = fmaf(p, f, -1.2420140846E-1f);
    p = fmaf(p, f,  1.4249322787E-1f);
    p = fmaf(p, f, -1.6668057665E-1f);
    p = fmaf(p, f,  2.0000714765E-1f);
    p = fmaf(p, f, -2.4999993993E-1f);
    p = fmaf(p, f,  3.3333331174E-1f);
    float y = p * f * z;
    y = fmaf(e, -2.12194440e-4f, y);
    y = fmaf(-0.5f, z, y);
    float r = f + y;
    r = fmaf(e, 0.693359375f, r);
    return r;
}
__device__ __forceinline__ float fexp(float x) {
    x = fmaxf(x, -87.0f);
    float t = x * 1.4426950408889634f;
    int   i = __float2int_rn(t);
    float fi = (float)i;
    float f = fmaf(fi, -0.693359375f, x);
    f = fmaf(fi, 2.12194440e-4f, f);
    float p = 1.9875691500E-4f;
    p = fmaf(p, f, 1.3981999507E-3f);
    p = fmaf(p, f, 8.3334519073E-3f);
    p = fmaf(p, f, 4.1665795894E-2f);
    p = fmaf(p, f, 1.6666665459E-1f);
    p = fmaf(p, f, 5.0000001201E-1f);
    float r = fmaf(p, f * f, f) + 1.0f;
    return r * __int_as_float((i + 127) << 23);
}

// ---------------- PTX helpers -------------------------------------------------
__device__ __forceinline__ uint32_t smem_u32(const void* p) {
    uint32_t a;
    asm("{ .reg .u64 t; cvta.to.shared.u64 t, %1; cvt.u32.u64 %0, t; }"
        : "=r"(a) : "l"(p));
    return a;
}
#define LDMATRIX_X4(r0, r1, r2, r3, addr) \
    asm volatile("ldmatrix.sync.aligned.m8n8.x4.shared.b16 {%0,%1,%2,%3}, [%4];" \
                 : "=r"(r0), "=r"(r1), "=r"(r2), "=r"(r3) : "r"(addr))
#define MMA16816(d, a, b0, b1) \
    asm volatile("mma.sync.aligned.m16n8k16.row.col.f32.bf16.bf16.f32 " \
                 "{%0,%1,%2,%3}, {%4,%5,%6,%7}, {%8,%9}, {%0,%1,%2,%3};" \
                 : "+f"((d)[0]), "+f"((d)[1]), "+f"((d)[2]), "+f"((d)[3]) \
                 : "r"((a)[0]), "r"((a)[1]), "r"((a)[2]), "r"((a)[3]), \
                   "r"(b0), "r"(b1))
#define CP_ASYNC16(dst, src) \
    asm volatile("cp.async.cg.shared.global [%0], [%1], 16;" \
                 :: "r"(dst), "l"(src) : "memory")
#define CP_COMMIT() asm volatile("cp.async.commit_group;" ::: "memory")
#define CP_WAIT0()  asm volatile("cp.async.wait_group 0;" ::: "memory")

// smem layout (bytes): A[buf][split]: 128 rows x 48B; B[buf][split]: 320 x 48B
#define A_OFF(buf, s) ((buf) * 12288 + (s) * 6144)
#define B_OFF(buf, s) (24576 + (buf) * 30720 + (s) * 15360)
#define GEMM_SMEM 86016

__device__ __forceinline__ uint32_t pkbf(__nv_bfloat16 a, __nv_bfloat16 b) {
    return (uint32_t)__bfloat16_as_ushort(a) | ((uint32_t)__bfloat16_as_ushort(b) << 16);
}

// ---------------- kernel: zero accumulators -----------------------------------
__global__ void zero_kernel() {
    int t = blockIdx.x * blockDim.x + threadIdx.x;
    if (t < GK) { g_prob[t] = 0.0f; g_cnt[t] = 0; }
    if (t == GK) g_fix_cnt = 0;
}

// ---------------- kernel: W^T bf16 hi/mid split --------------------------------
__global__ void wsplit_kernel(const float* __restrict__ W) {
    int i = blockIdx.x * blockDim.x + threadIdx.x;
    if (i >= GK * DD) return;
    int n = i / DD, k = i - n * DD;
    float x = W[(size_t)k * GK + n];
    __nv_bfloat16 h = __float2bfloat16_rn(x);
    float r = x - __bfloat162float(h);
    __nv_bfloat16 m = __float2bfloat16_rn(r);
    g_wt[0][i] = h; g_wt[1][i] = m;
}

// ---------------- HMMA GEMM -----------------------------------------------------
// grid (2 groups, 256 M-blocks), 512 threads = 16 warps (4 Mw x 4 Nw).
// CTA tile 128 x 320; warp tile 32 x 80 = 2 x 10 m16n8k16 tiles.
__global__ __launch_bounds__(512, 1)
void gemm_hmma_kernel(const float* __restrict__ X, const float* __restrict__ bias) {
    extern __shared__ char sm[];
    const uint32_t smb = smem_u32(sm);
    const int tid  = threadIdx.x;
    const int lane = tid & 31;
    const int wid  = tid >> 5;
    const int wm   = wid & 3;    // M quadrant (32 rows)
    const int wn   = wid >> 2;   // N quadrant (80 cols)
    const int g    = blockIdx.x;
    const int bm   = blockIdx.y;

    float acc[2][10][4];
#pragma unroll
    for (int i = 0; i < 2; i++)
#pragma unroll
        for (int j = 0; j < 10; j++)
#pragma unroll
            for (int q = 0; q < 4; q++) acc[i][j][q] = 0.0f;

    // A-load thread mapping: row = tid/4 (0..127), q = tid%4 (float4 within k16)
    const int a_row = tid >> 2;
    const int a_q   = tid & 3;
    const float* Xrow = X + (size_t)(bm * 128 + a_row) * DD + a_q * 4;

    // prologue: chunk 0
    float4 av = *(const float4*)(Xrow);
    for (int idx = tid; idx < 1280; idx += 512) {
        int n = idx >> 2, rem = idx & 3, s = rem >> 1, h = rem & 1;
        const __nv_bfloat16* src = &g_wt[s][(size_t)(g * KC + n) * DD + h * 8];
        CP_ASYNC16(smb + B_OFF(0, s) + n * 48 + h * 16, src);
    }
    CP_COMMIT();
    {
        __nv_bfloat16 h0 = __float2bfloat16_rn(av.x), h1 = __float2bfloat16_rn(av.y);
        __nv_bfloat16 h2 = __float2bfloat16_rn(av.z), h3 = __float2bfloat16_rn(av.w);
        __nv_bfloat16 m0 = __float2bfloat16_rn(av.x - __bfloat162float(h0));
        __nv_bfloat16 m1 = __float2bfloat16_rn(av.y - __bfloat162float(h1));
        __nv_bfloat16 m2 = __float2bfloat16_rn(av.z - __bfloat162float(h2));
        __nv_bfloat16 m3 = __float2bfloat16_rn(av.w - __bfloat162float(h3));
        *(uint2*)(sm + A_OFF(0, 0) + a_row * 48 + a_q * 8) = make_uint2(pkbf(h0, h1), pkbf(h2, h3));
        *(uint2*)(sm + A_OFF(0, 1) + a_row * 48 + a_q * 8) = make_uint2(pkbf(m0, m1), pkbf(m2, m3));
    }
    CP_WAIT0();
    __syncthreads();

    // ldmatrix address components (byte offsets within a tile)
    const int a_lrow = (lane & 15);
    const int a_lcol = (lane >> 4) * 16;
    const int b_lrow = (lane & 7) + ((lane >> 4) & 1) * 8;
    const int b_lcol = ((lane >> 3) & 1) * 16;

    int buf = 0;
    for (int t = 0; t < NCHUNK; t++) {
        float4 nv;
        if (t + 1 < NCHUNK) {
            nv = *(const float4*)(Xrow + (t + 1) * 16);
            const int k0 = (t + 1) * 16;
            for (int idx = tid; idx < 1280; idx += 512) {
                int n = idx >> 2, rem = idx & 3, s = rem >> 1, h = rem & 1;
                const __nv_bfloat16* src = &g_wt[s][(size_t)(g * KC + n) * DD + k0 + h * 8];
                CP_ASYNC16(smb + B_OFF(buf ^ 1, s) + n * 48 + h * 16, src);
            }
            CP_COMMIT();
        }

        // ---- compute chunk t ----
        uint32_t ah[2][4], am[2][4];
#pragma unroll
        for (int mt = 0; mt < 2; mt++) {
            const int row = wm * 32 + mt * 16 + a_lrow;
            LDMATRIX_X4(ah[mt][0], ah[mt][1], ah[mt][2], ah[mt][3],
                        smb + A_OFF(buf, 0) + row * 48 + a_lcol);
            LDMATRIX_X4(am[mt][0], am[mt][1], am[mt][2], am[mt][3],
                        smb + A_OFF(buf, 1) + row * 48 + a_lcol);
        }
#pragma unroll
        for (int bg = 0; bg < 5; bg++) {
            const int nrow = wn * 80 + bg * 16 + b_lrow;
            uint32_t bh[4], bm4[4];
            LDMATRIX_X4(bh[0], bh[1], bh[2], bh[3],
                        smb + B_OFF(buf, 0) + nrow * 48 + b_lcol);
            LDMATRIX_X4(bm4[0], bm4[1], bm4[2], bm4[3],
                        smb + B_OFF(buf, 1) + nrow * 48 + b_lcol);
#pragma unroll
            for (int mt = 0; mt < 2; mt++) {
#pragma unroll
                for (int h2 = 0; h2 < 2; h2++) {
                    float* d = acc[mt][bg * 2 + h2];
                    MMA16816(d, ah[mt], bh[h2 * 2],  bh[h2 * 2 + 1]);
                    MMA16816(d, ah[mt], bm4[h2 * 2], bm4[h2 * 2 + 1]);
                    MMA16816(d, am[mt], bh[h2 * 2],  bh[h2 * 2 + 1]);
                }
            }
        }

        if (t + 1 < NCHUNK) {
            __nv_bfloat16 h0 = __float2bfloat16_rn(nv.x), h1 = __float2bfloat16_rn(nv.y);
            __nv_bfloat16 h2 = __float2bfloat16_rn(nv.z), h3 = __float2bfloat16_rn(nv.w);
            __nv_bfloat16 m0 = __float2bfloat16_rn(nv.x - __bfloat162float(h0));
            __nv_bfloat16 m1 = __float2bfloat16_rn(nv.y - __bfloat162float(h1));
            __nv_bfloat16 m2 = __float2bfloat16_rn(nv.z - __bfloat162float(h2));
            __nv_bfloat16 m3 = __float2bfloat16_rn(nv.w - __bfloat162float(h3));
            *(uint2*)(sm + A_OFF(buf ^ 1, 0) + a_row * 48 + a_q * 8) = make_uint2(pkbf(h0, h1), pkbf(h2, h3));
            *(uint2*)(sm + A_OFF(buf ^ 1, 1) + a_row * 48 + a_q * 8) = make_uint2(pkbf(m0, m1), pkbf(m2, m3));
            CP_WAIT0();
        }
        __syncthreads();
        buf ^= 1;
    }

    // ---- store D + bias -> g_logits ([pair][KC], pair = row*2 + g) ----
#pragma unroll
    for (int nt = 0; nt < 10; nt++) {
        const int c = wn * 80 + nt * 8 + (lane & 3) * 2;
        const float b0 = bias[g * KC + c];
        const float b1 = bias[g * KC + c + 1];
#pragma unroll
        for (int mt = 0; mt < 2; mt++) {
            const int r0 = bm * 128 + wm * 32 + mt * 16 + (lane >> 2);
            float* p0 = g_logits + ((size_t)r0 * 2 + g) * KC + c;
            float* p1 = g_logits + ((size_t)(r0 + 8) * 2 + g) * KC + c;
            p0[0] = acc[mt][nt][0] + b0;  p0[1] = acc[mt][nt][1] + b1;
            p1[0] = acc[mt][nt][2] + b0;  p1[1] = acc[mt][nt][3] + b1;
        }
    }
}

// ---------------- fused epilogue (round-1 proven + near-tie recording) ---------
__global__ __launch_bounds__(256)
void epilogue_kernel(const float* __restrict__ noise,
                     const float* __restrict__ cb,
                     float* __restrict__ out) {
    __shared__ float s_prob[GK];
    __shared__ int   s_cnt[GK];
    const int tid = threadIdx.x;
    for (int i = tid; i < GK; i += 256) { s_prob[i] = 0.0f; s_cnt[i] = 0; }
    __syncthreads();

    const int lane = tid & 31;
    const int warp = tid >> 5;
    const int pair0 = (blockIdx.x * 8 + warp) * 16;

    for (int pp = 0; pp < 16; pp++) {
        const int pair = pair0 + pp;
        const int r = pair >> 1;
        const int g = pair & 1;
        const float* lrow = g_logits + (size_t)pair * KC;
        const float* nrow = noise    + (size_t)pair * KC;

        float l[10], gl[10];
#pragma unroll
        for (int j = 0; j < 10; j++) {
            const int k = lane + 32 * j;
            const float lv = lrow[k];
            float u = nrow[k];
            u = fmaf(u, 0.999998f, 1e-6f);
            const float gum = -flog(-flog(u));
            l[j]  = lv;
            gl[j] = lv + gum;
        }

        // hard top-2 (value M, index I, runner-up M2)
        float M = l[0], M2 = -3.4e38f; int I = lane;
#pragma unroll
        for (int j = 1; j < 10; j++) {
            if (l[j] > M) { M2 = M; M = l[j]; I = lane + 32 * j; }
            else if (l[j] > M2) M2 = l[j];
        }
#pragma unroll
        for (int off = 16; off; off >>= 1) {
            float ov = __shfl_down_sync(0xffffffffu, M, off);
            int   oi = __shfl_down_sync(0xffffffffu, I, off);
            float o2 = __shfl_down_sync(0xffffffffu, M2, off);
            if (ov > M || (ov == M && oi < I)) { M2 = fmaxf(M, o2); M = ov; I = oi; }
            else                                { M2 = fmaxf(M2, ov); }
        }
        M  = __shfl_sync(0xffffffffu, M, 0);
        M2 = __shfl_sync(0xffffffffu, M2, 0);
        I  = __shfl_sync(0xffffffffu, I, 0);

        // gumbel top-2
        float GM = gl[0], GM2 = -3.4e38f; int GI = lane;
#pragma unroll
        for (int j = 1; j < 10; j++) {
            if (gl[j] > GM) { GM2 = GM; GM = gl[j]; GI = lane + 32 * j; }
            else if (gl[j] > GM2) GM2 = gl[j];
        }
#pragma unroll
        for (int off = 16; off; off >>= 1) {
            float ov = __shfl_down_sync(0xffffffffu, GM, off);
            int   oi = __shfl_down_sync(0xffffffffu, GI, off);
            float o2 = __shfl_down_sync(0xffffffffu, GM2, off);
            if (ov > GM || (ov == GM && oi < GI)) { GM2 = fmaxf(GM, o2); GM = ov; GI = oi; }
            else                                   { GM2 = fmaxf(GM2, ov); }
        }
        GM  = __shfl_sync(0xffffffffu, GM, 0);
        GM2 = __shfl_sync(0xffffffffu, GM2, 0);
        GI  = __shfl_sync(0xffffffffu, GI, 0);

        // softmax(logits) accumulation
        float e[10];
        float s = 0.0f;
#pragma unroll
        for (int j = 0; j < 10; j++) { e[j] = fexp(l[j] - M); s += e[j]; }
#pragma unroll
        for (int off = 16; off; off >>= 1)
            s += __shfl_xor_sync(0xffffffffu, s, off);
        const float inv = 1.0f / s;

        const int kb = g * KC;
#pragma unroll
        for (int j = 0; j < 10; j++)
            atomicAdd(&s_prob[kb + lane + 32 * j], e[j] * inv);
        if (lane == 0) {
            atomicAdd(&s_cnt[kb + I], 1);
            if (M - M2 < THETA || GM - GM2 < THETA) {
                int pos = atomicAdd(&g_fix_cnt, 1);
                g_fix[pos] = make_int2(pair, I);
            }
        }

        const float4* src = (const float4*)(cb + ((size_t)kb + GI) * VDIM);
        float4*       dst = (float4*)(out + (size_t)r * 256 + g * VDIM);
        dst[lane] = src[lane];
    }

    __syncthreads();
    for (int i = tid; i < GK; i += 256) {
        atomicAdd(&g_prob[i], s_prob[i]);
        atomicAdd(&g_cnt[i],  s_cnt[i]);
    }
}

// ---------------- fixup: exact recompute of near-tie rows ----------------------
// One block (320 threads) per listed pair; ascending-k FMA chain bit-matches the
// round-1 reference-tracking arithmetic.
__global__ __launch_bounds__(320)
void fixup_kernel(const float* __restrict__ X, const float* __restrict__ W,
                  const float* __restrict__ bias, const float* __restrict__ noise,
                  const float* __restrict__ cb, float* __restrict__ out) {
    __shared__ float sl[KC], sgl[KC];
    __shared__ int sI[2];
    const int n = threadIdx.x;
    const int total = g_fix_cnt;

    for (int f = blockIdx.x; f < total; f += gridDim.x) {
        const int2 rec = g_fix[f];
        const int pair = rec.x, Iapp = rec.y;
        const int r = pair >> 1, g = pair & 1;
        const float* xr = X + (size_t)r * DD;
        const int col = g * KC + n;

        float acc = 0.0f;
        for (int k = 0; k < DD; k++)
            acc = fmaf(xr[k], W[(size_t)k * GK + col], acc);
        const float lg = acc + bias[col];

        float u = noise[(size_t)pair * KC + n];
        u = fmaf(u, 0.999998f, 1e-6f);
        const float glv = lg - flog(-flog(u));

        sl[n] = lg; sgl[n] = glv;
        __syncthreads();
        if (n == 0) {
            int bi = 0; float bv = sl[0];
            for (int k = 1; k < KC; k++) if (sl[k] > bv) { bv = sl[k]; bi = k; }
            sI[0] = bi;
            bi = 0; bv = sgl[0];
            for (int k = 1; k < KC; k++) if (sgl[k] > bv) { bv = sgl[k]; bi = k; }
            sI[1] = bi;
        }
        __syncthreads();

        const int kb = g * KC;
        if (n == 0 && sI[0] != Iapp) {
            atomicSub(&g_cnt[kb + Iapp], 1);
            atomicAdd(&g_cnt[kb + sI[0]], 1);
        }
        if (n < VDIM)
            out[(size_t)r * 256 + g * VDIM + n] = cb[((size_t)kb + sI[1]) * VDIM + n];
        __syncthreads();
    }
}

// ---------------- perplexity scalars --------------------------------------------
__global__ void finalize_kernel(float* __restrict__ out, int scalar_base) {
    __shared__ float sh[GK], sp[GK];
    const int t = threadIdx.x;
    if (t < GK) {
        float hp = (float)g_cnt[t] * (1.0f / (float)BT);
        float ap = g_prob[t]       * (1.0f / (float)BT);
        sh[t] = hp * logf(hp + 1e-7f);
        sp[t] = ap * logf(ap + 1e-7f);
    }
    __syncthreads();
    if (t == 0) {
        float h0 = 0.f, h1 = 0.f, p0 = 0.f, p1 = 0.f;
        for (int k = 0; k < KC; k++) {
            h0 += sh[k]; h1 += sh[KC + k];
            p0 += sp[k]; p1 += sp[KC + k];
        }
        out[scalar_base]     = expf(-h0) + expf(-h1);
        out[scalar_base + 1] = expf(-p0) + expf(-p1);
    }
}

// ---------------- launch ----------------------------------------------------------
extern "C" void kernel_launch(void* const* d_in, const int* in_sizes, int n_in,
                              void* d_out, int out_size) {
    const float* x     = (const float*)d_in[0];  // [32768,768]
    const float* W     = (const float*)d_in[1];  // [768,640]
    const float* bias  = (const float*)d_in[2];  // [640]
    const float* cb    = (const float*)d_in[3];  // [640,128]
    const float* noise = (const float*)d_in[4];  // [32768,640]
    float* out = (float*)d_out;

    cudaFuncSetAttribute(gemm_hmma_kernel,
                         cudaFuncAttributeMaxDynamicSharedMemorySize, GEMM_SMEM);

    zero_kernel<<<3, 256>>>();
    wsplit_kernel<<<(GK * DD + 255) / 256, 256>>>(W);
    dim3 grid(2, 256);
    gemm_hmma_kernel<<<grid, 512, GEMM_SMEM>>>(x, bias);
    epilogue_kernel<<<512, 256>>>(noise, cb, out);
    fixup_kernel<<<512, 320>>>(x, W, bias, noise, cb, out);
    finalize_kernel<<<1, GK>>>(out, out_size - 2);
}

// round 4
// speedup vs baseline: 1.4628x; 1.0799x over previous
#include <cuda_runtime.h>
#include <cuda_bf16.h>
#include <cstdint>

// ---------------------------------------------------------------------------
// GumbelVectorQuantizer on GB300 (sm_103 baseline ISA path):
//   logits = x@W + b via HMMA (mma.sync m16n8k16 bf16) 2-split emulated fp32
//            (MMA stream reordered: no back-to-back RAW on accumulators)
//   epilogue: gumbel argmax gather + perplexities (MUFU log/exp, reg-accum probs)
//   fixup:    exact sequential-FMA recompute of near-tie rows (bit-tracks ref)
// ---------------------------------------------------------------------------

#define BT     32768
#define DD     768
#define GK     640
#define KC     320
#define VDIM   128
#define NCHUNK 48
#define THETA  4e-3f
#define MAXFIX 65536

__device__ float g_logits[(size_t)BT * GK];                    // 83.9 MB
__device__ float g_prob[GK];
__device__ int   g_cnt[GK];
__device__ __align__(16) __nv_bfloat16 g_wt[2][(size_t)GK * DD];
__device__ int   g_fix_cnt;
__device__ int2  g_fix[MAXFIX];

// ---------------- exact-path log (FMA pipe, ~1 ulp; round-1 validated) --------
__device__ __forceinline__ float flog(float x) {
    int xi = __float_as_int(x);
    float e = (float)(((xi >> 23) & 0xFF) - 126);
    float m = __int_as_float((xi & 0x007FFFFF) | 0x3F000000);
    if (m < 0.70710678f) { m += m; e -= 1.0f; }
    float f = m - 1.0f;
    float z = f * f;
    float p = 7.0376836292E-2f;
    p = fmaf(p, f, -1.1514610310E-1f);
    p = fmaf(p, f,  1.1676998740E-1f);
    p = fmaf(p, f, -1.2420140846E-1f);
    p = fmaf(p, f,  1.4249322787E-1f);
    p = fmaf(p, f, -1.6668057665E-1f);
    p = fmaf(p, f,  2.0000714765E-1f);
    p = fmaf(p, f, -2.4999993993E-1f);
    p = fmaf(p, f,  3.3333331174E-1f);
    float y = p * f * z;
    y = fmaf(e, -2.12194440e-4f, y);
    y = fmaf(-0.5f, z, y);
    float r = f + y;
    r = fmaf(e, 0.693359375f, r);
    return r;
}

// ---------------- PTX helpers --------------------------------------------------
__device__ __forceinline__ uint32_t smem_u32(const void* p) {
    uint32_t a;
    asm("{ .reg .u64 t; cvta.to.shared.u64 t, %1; cvt.u32.u64 %0, t; }"
        : "=r"(a) : "l"(p));
    return a;
}
#define LDMATRIX_X4(r0, r1, r2, r3, addr) \
    asm volatile("ldmatrix.sync.aligned.m8n8.x4.shared.b16 {%0,%1,%2,%3}, [%4];" \
                 : "=r"(r0), "=r"(r1), "=r"(r2), "=r"(r3) : "r"(addr))
#define MMA16816(d, a, b0, b1) \
    asm volatile("mma.sync.aligned.m16n8k16.row.col.f32.bf16.bf16.f32 " \
                 "{%0,%1,%2,%3}, {%4,%5,%6,%7}, {%8,%9}, {%0,%1,%2,%3};" \
                 : "+f"((d)[0]), "+f"((d)[1]), "+f"((d)[2]), "+f"((d)[3]) \
                 : "r"((a)[0]), "r"((a)[1]), "r"((a)[2]), "r"((a)[3]), \
                   "r"(b0), "r"(b1))
#define CP_ASYNC16(dst, src) \
    asm volatile("cp.async.cg.shared.global [%0], [%1], 16;" \
                 :: "r"(dst), "l"(src) : "memory")
#define CP_COMMIT() asm volatile("cp.async.commit_group;" ::: "memory")
#define CP_WAIT0()  asm volatile("cp.async.wait_group 0;" ::: "memory")

#define A_OFF(buf, s) ((buf) * 12288 + (s) * 6144)
#define B_OFF(buf, s) (24576 + (buf) * 30720 + (s) * 15360)
#define GEMM_SMEM 86016

__device__ __forceinline__ uint32_t pkbf(__nv_bfloat16 a, __nv_bfloat16 b) {
    return (uint32_t)__bfloat16_as_ushort(a) | ((uint32_t)__bfloat16_as_ushort(b) << 16);
}

// ---------------- zero ----------------------------------------------------------
__global__ void zero_kernel() {
    int t = blockIdx.x * blockDim.x + threadIdx.x;
    if (t < GK) { g_prob[t] = 0.0f; g_cnt[t] = 0; }
    if (t == GK) g_fix_cnt = 0;
}

// ---------------- W^T split via tiled transpose (coalesced both sides) ----------
__global__ __launch_bounds__(256)
void wsplit_kernel(const float* __restrict__ W) {
    __shared__ float tile[32][33];
    const int n0 = blockIdx.x * 32;   // 20 blocks
    const int k0 = blockIdx.y * 32;   // 24 blocks
    const int tx = threadIdx.x & 31;
    const int ty = threadIdx.x >> 5;  // 0..7
#pragma unroll
    for (int i = 0; i < 32; i += 8)
        tile[ty + i][tx] = W[(size_t)(k0 + ty + i) * GK + n0 + tx];
    __syncthreads();
#pragma unroll
    for (int i = 0; i < 32; i += 8) {
        const int n = n0 + ty + i, k = k0 + tx;
        float x = tile[tx][ty + i];
        __nv_bfloat16 h = __float2bfloat16_rn(x);
        __nv_bfloat16 m = __float2bfloat16_rn(x - __bfloat162float(h));
        g_wt[0][(size_t)n * DD + k] = h;
        g_wt[1][(size_t)n * DD + k] = m;
    }
}

// ---------------- HMMA GEMM ------------------------------------------------------
__global__ __launch_bounds__(512, 1)
void gemm_hmma_kernel(const float* __restrict__ X, const float* __restrict__ bias) {
    extern __shared__ char sm[];
    const uint32_t smb = smem_u32(sm);
    const int tid  = threadIdx.x;
    const int lane = tid & 31;
    const int wid  = tid >> 5;
    const int wm   = wid & 3;
    const int wn   = wid >> 2;
    const int g    = blockIdx.x;
    const int bm   = blockIdx.y;

    float acc[2][10][4];
#pragma unroll
    for (int i = 0; i < 2; i++)
#pragma unroll
        for (int j = 0; j < 10; j++)
#pragma unroll
            for (int q = 0; q < 4; q++) acc[i][j][q] = 0.0f;

    const int a_row = tid >> 2;
    const int a_q   = tid & 3;
    const float* Xrow = X + (size_t)(bm * 128 + a_row) * DD + a_q * 4;

    // prologue: chunk 0
    float4 av = *(const float4*)(Xrow);
    for (int idx = tid; idx < 1280; idx += 512) {
        int n = idx >> 2, rem = idx & 3, s = rem >> 1, h = rem & 1;
        const __nv_bfloat16* src = &g_wt[s][(size_t)(g * KC + n) * DD + h * 8];
        CP_ASYNC16(smb + B_OFF(0, s) + n * 48 + h * 16, src);
    }
    CP_COMMIT();
    {
        __nv_bfloat16 h0 = __float2bfloat16_rn(av.x), h1 = __float2bfloat16_rn(av.y);
        __nv_bfloat16 h2 = __float2bfloat16_rn(av.z), h3 = __float2bfloat16_rn(av.w);
        __nv_bfloat16 m0 = __float2bfloat16_rn(av.x - __bfloat162float(h0));
        __nv_bfloat16 m1 = __float2bfloat16_rn(av.y - __bfloat162float(h1));
        __nv_bfloat16 m2 = __float2bfloat16_rn(av.z - __bfloat162float(h2));
        __nv_bfloat16 m3 = __float2bfloat16_rn(av.w - __bfloat162float(h3));
        *(uint2*)(sm + A_OFF(0, 0) + a_row * 48 + a_q * 8) = make_uint2(pkbf(h0, h1), pkbf(h2, h3));
        *(uint2*)(sm + A_OFF(0, 1) + a_row * 48 + a_q * 8) = make_uint2(pkbf(m0, m1), pkbf(m2, m3));
    }
    CP_WAIT0();
    __syncthreads();

    const int a_lrow = (lane & 15);
    const int a_lcol = (lane >> 4) * 16;
    const int b_lrow = (lane & 7) + ((lane >> 4) & 1) * 8;
    const int b_lcol = ((lane >> 3) & 1) * 16;
    const int b_nbase = (wn * 80 + b_lrow) * 48 + b_lcol;

    int buf = 0;
    for (int t = 0; t < NCHUNK; t++) {
        float4 nv;
        if (t + 1 < NCHUNK) {
            nv = *(const float4*)(Xrow + (t + 1) * 16);
            const int k0 = (t + 1) * 16;
            for (int idx = tid; idx < 1280; idx += 512) {
                int n = idx >> 2, rem = idx & 3, s = rem >> 1, h = rem & 1;
                const __nv_bfloat16* src = &g_wt[s][(size_t)(g * KC + n) * DD + k0 + h * 8];
                CP_ASYNC16(smb + B_OFF(buf ^ 1, s) + n * 48 + h * 16, src);
            }
            CP_COMMIT();
        }

        // ---- compute chunk t (reordered: no RAW-adjacent MMAs) ----
        uint32_t ah[2][4], am[2][4];
#pragma unroll
        for (int mt = 0; mt < 2; mt++) {
            const int row = wm * 32 + mt * 16 + a_lrow;
            LDMATRIX_X4(ah[mt][0], ah[mt][1], ah[mt][2], ah[mt][3],
                        smb + A_OFF(buf, 0) + row * 48 + a_lcol);
            LDMATRIX_X4(am[mt][0], am[mt][1], am[mt][2], am[mt][3],
                        smb + A_OFF(buf, 1) + row * 48 + a_lcol);
        }

        uint32_t bb[2][4];
        // ---- pass 1: B_hi with both A_hi and A_mid (8 MMAs per bg) ----
        LDMATRIX_X4(bb[0][0], bb[0][1], bb[0][2], bb[0][3],
                    smb + B_OFF(buf, 0) + b_nbase);
#pragma unroll
        for (int bg = 0; bg < 5; bg++) {
            const int cur = bg & 1, nxt = cur ^ 1;
            if (bg < 4)
                LDMATRIX_X4(bb[nxt][0], bb[nxt][1], bb[nxt][2], bb[nxt][3],
                            smb + B_OFF(buf, 0) + b_nbase + (bg + 1) * 16 * 48);
#pragma unroll
            for (int h2 = 0; h2 < 2; h2++) {
                MMA16816(acc[0][bg * 2 + h2], ah[0], bb[cur][h2 * 2], bb[cur][h2 * 2 + 1]);
                MMA16816(acc[1][bg * 2 + h2], ah[1], bb[cur][h2 * 2], bb[cur][h2 * 2 + 1]);
            }
#pragma unroll
            for (int h2 = 0; h2 < 2; h2++) {
                MMA16816(acc[0][bg * 2 + h2], am[0], bb[cur][h2 * 2], bb[cur][h2 * 2 + 1]);
                MMA16816(acc[1][bg * 2 + h2], am[1], bb[cur][h2 * 2], bb[cur][h2 * 2 + 1]);
            }
        }
        // ---- pass 2: B_mid with A_hi (4 MMAs per bg) ----
        LDMATRIX_X4(bb[0][0], bb[0][1], bb[0][2], bb[0][3],
                    smb + B_OFF(buf, 1) + b_nbase);
#pragma unroll
        for (int bg = 0; bg < 5; bg++) {
            const int cur = bg & 1, nxt = cur ^ 1;
            if (bg < 4)
                LDMATRIX_X4(bb[nxt][0], bb[nxt][1], bb[nxt][2], bb[nxt][3],
                            smb + B_OFF(buf, 1) + b_nbase + (bg + 1) * 16 * 48);
#pragma unroll
            for (int h2 = 0; h2 < 2; h2++) {
                MMA16816(acc[0][bg * 2 + h2], ah[0], bb[cur][h2 * 2], bb[cur][h2 * 2 + 1]);
                MMA16816(acc[1][bg * 2 + h2], ah[1], bb[cur][h2 * 2], bb[cur][h2 * 2 + 1]);
            }
        }

        if (t + 1 < NCHUNK) {
            __nv_bfloat16 h0 = __float2bfloat16_rn(nv.x), h1 = __float2bfloat16_rn(nv.y);
            __nv_bfloat16 h2 = __float2bfloat16_rn(nv.z), h3 = __float2bfloat16_rn(nv.w);
            __nv_bfloat16 m0 = __float2bfloat16_rn(nv.x - __bfloat162float(h0));
            __nv_bfloat16 m1 = __float2bfloat16_rn(nv.y - __bfloat162float(h1));
            __nv_bfloat16 m2 = __float2bfloat16_rn(nv.z - __bfloat162float(h2));
            __nv_bfloat16 m3 = __float2bfloat16_rn(nv.w - __bfloat162float(h3));
            *(uint2*)(sm + A_OFF(buf ^ 1, 0) + a_row * 48 + a_q * 8) = make_uint2(pkbf(h0, h1), pkbf(h2, h3));
            *(uint2*)(sm + A_OFF(buf ^ 1, 1) + a_row * 48 + a_q * 8) = make_uint2(pkbf(m0, m1), pkbf(m2, m3));
            CP_WAIT0();
        }
        __syncthreads();
        buf ^= 1;
    }

    // ---- store D + bias -> g_logits ----
#pragma unroll
    for (int nt = 0; nt < 10; nt++) {
        const int c = wn * 80 + nt * 8 + (lane & 3) * 2;
        const float b0 = bias[g * KC + c];
        const float b1 = bias[g * KC + c + 1];
#pragma unroll
        for (int mt = 0; mt < 2; mt++) {
            const int r0 = bm * 128 + wm * 32 + mt * 16 + (lane >> 2);
            float* p0 = g_logits + ((size_t)r0 * 2 + g) * KC + c;
            float* p1 = g_logits + ((size_t)(r0 + 8) * 2 + g) * KC + c;
            p0[0] = acc[mt][nt][0] + b0;  p0[1] = acc[mt][nt][1] + b1;
            p1[0] = acc[mt][nt][2] + b0;  p1[1] = acc[mt][nt][3] + b1;
        }
    }
}

// ---------------- fused epilogue (MUFU transcendentals, reg-accum probs) --------
__global__ __launch_bounds__(256)
void epilogue_kernel(const float* __restrict__ noise,
                     const float* __restrict__ cb,
                     float* __restrict__ out) {
    __shared__ float s_prob[GK];
    __shared__ int   s_cnt[GK];
    const int tid = threadIdx.x;
    for (int i = tid; i < GK; i += 256) { s_prob[i] = 0.0f; s_cnt[i] = 0; }
    __syncthreads();

    const int lane = tid & 31;
    const int warp = tid >> 5;
    const int pair0 = (blockIdx.x * 8 + warp) * 16;

    float pacc[2][10];
#pragma unroll
    for (int g2 = 0; g2 < 2; g2++)
#pragma unroll
        for (int j = 0; j < 10; j++) pacc[g2][j] = 0.0f;

    for (int pp = 0; pp < 16; pp++) {
        const int pair = pair0 + pp;
        const int r = pair >> 1;
        const int g = pair & 1;
        const float* lrow = g_logits + (size_t)pair * KC;
        const float* nrow = noise    + (size_t)pair * KC;

        float l[10], gl[10];
#pragma unroll
        for (int j = 0; j < 10; j++) {
            const int k = lane + 32 * j;
            const float lv = lrow[k];
            float u = nrow[k];
            u = fmaf(u, 0.999998f, 1e-6f);
            const float gum = -__logf(-__logf(u));   // MUFU path; fixup covers ties
            l[j]  = lv;
            gl[j] = lv + gum;
        }

        // hard top-2
        float M = l[0], M2 = -3.4e38f; int I = lane;
#pragma unroll
        for (int j = 1; j < 10; j++) {
            if (l[j] > M) { M2 = M; M = l[j]; I = lane + 32 * j; }
            else if (l[j] > M2) M2 = l[j];
        }
#pragma unroll
        for (int off = 16; off; off >>= 1) {
            float ov = __shfl_down_sync(0xffffffffu, M, off);
            int   oi = __shfl_down_sync(0xffffffffu, I, off);
            float o2 = __shfl_down_sync(0xffffffffu, M2, off);
            if (ov > M || (ov == M && oi < I)) { M2 = fmaxf(M, o2); M = ov; I = oi; }
            else                                { M2 = fmaxf(M2, ov); }
        }
        M  = __shfl_sync(0xffffffffu, M, 0);
        M2 = __shfl_sync(0xffffffffu, M2, 0);
        I  = __shfl_sync(0xffffffffu, I, 0);

        // gumbel top-2
        float GM = gl[0], GM2 = -3.4e38f; int GI = lane;
#pragma unroll
        for (int j = 1; j < 10; j++) {
            if (gl[j] > GM) { GM2 = GM; GM = gl[j]; GI = lane + 32 * j; }
            else if (gl[j] > GM2) GM2 = gl[j];
        }
#pragma unroll
        for (int off = 16; off; off >>= 1) {
            float ov = __shfl_down_sync(0xffffffffu, GM, off);
            int   oi = __shfl_down_sync(0xffffffffu, GI, off);
            float o2 = __shfl_down_sync(0xffffffffu, GM2, off);
            if (ov > GM || (ov == GM && oi < GI)) { GM2 = fmaxf(GM, o2); GM = ov; GI = oi; }
            else                                   { GM2 = fmaxf(GM2, ov); }
        }
        GM  = __shfl_sync(0xffffffffu, GM, 0);
        GM2 = __shfl_sync(0xffffffffu, GM2, 0);
        GI  = __shfl_sync(0xffffffffu, GI, 0);

        // softmax accumulation (registers; flushed once per thread at the end)
        float e[10];
        float s = 0.0f;
#pragma unroll
        for (int j = 0; j < 10; j++) { e[j] = __expf(l[j] - M); s += e[j]; }
#pragma unroll
        for (int off = 16; off; off >>= 1)
            s += __shfl_xor_sync(0xffffffffu, s, off);
        const float inv = 1.0f / s;
#pragma unroll
        for (int j = 0; j < 10; j++) pacc[g][j] += e[j] * inv;

        if (lane == 0) {
            atomicAdd(&s_cnt[g * KC + I], 1);
            if (M - M2 < THETA || GM - GM2 < THETA) {
                int pos = atomicAdd(&g_fix_cnt, 1);
                g_fix[pos] = make_int2(pair, I);
            }
        }

        const float4* src = (const float4*)(cb + ((size_t)(g * KC) + GI) * VDIM);
        float4*       dst = (float4*)(out + (size_t)r * 256 + g * VDIM);
        dst[lane] = src[lane];
    }

#pragma unroll
    for (int g2 = 0; g2 < 2; g2++)
#pragma unroll
        for (int j = 0; j < 10; j++)
            atomicAdd(&s_prob[g2 * KC + lane + 32 * j], pacc[g2][j]);

    __syncthreads();
    for (int i = tid; i < GK; i += 256) {
        atomicAdd(&g_prob[i], s_prob[i]);
        atomicAdd(&g_cnt[i],  s_cnt[i]);
    }
}

// ---------------- fixup: exact recompute of near-tie rows ------------------------
__global__ __launch_bounds__(320)
void fixup_kernel(const float* __restrict__ X, const float* __restrict__ W,
                  const float* __restrict__ bias, const float* __restrict__ noise,
                  const float* __restrict__ cb, float* __restrict__ out) {
    __shared__ float sl[KC], sgl[KC];
    __shared__ int sI[2];
    const int n = threadIdx.x;
    const int total = g_fix_cnt;

    for (int f = blockIdx.x; f < total; f += gridDim.x) {
        const int2 rec = g_fix[f];
        const int pair = rec.x, Iapp = rec.y;
        const int r = pair >> 1, g = pair & 1;
        const float* xr = X + (size_t)r * DD;
        const int col = g * KC + n;

        float acc = 0.0f;
        for (int k = 0; k < DD; k++)
            acc = fmaf(xr[k], W[(size_t)k * GK + col], acc);
        const float lg = acc + bias[col];

        float u = noise[(size_t)pair * KC + n];
        u = fmaf(u, 0.999998f, 1e-6f);
        const float glv = lg - flog(-flog(u));

        sl[n] = lg; sgl[n] = glv;
        __syncthreads();
        if (n == 0) {
            int bi = 0; float bv = sl[0];
            for (int k = 1; k < KC; k++) if (sl[k] > bv) { bv = sl[k]; bi = k; }
            sI[0] = bi;
            bi = 0; bv = sgl[0];
            for (int k = 1; k < KC; k++) if (sgl[k] > bv) { bv = sgl[k]; bi = k; }
            sI[1] = bi;
        }
        __syncthreads();

        const int kb = g * KC;
        if (n == 0 && sI[0] != Iapp) {
            atomicSub(&g_cnt[kb + Iapp], 1);
            atomicAdd(&g_cnt[kb + sI[0]], 1);
        }
        if (n < VDIM)
            out[(size_t)r * 256 + g * VDIM + n] = cb[((size_t)kb + sI[1]) * VDIM + n];
        __syncthreads();
    }
}

// ---------------- perplexity scalars -----------------------------------------------
__global__ void finalize_kernel(float* __restrict__ out, int scalar_base) {
    __shared__ float sh[GK], sp[GK];
    const int t = threadIdx.x;
    if (t < GK) {
        float hp = (float)g_cnt[t] * (1.0f / (float)BT);
        float ap = g_prob[t]       * (1.0f / (float)BT);
        sh[t] = hp * logf(hp + 1e-7f);
        sp[t] = ap * logf(ap + 1e-7f);
    }
    __syncthreads();
    if (t == 0) {
        float h0 = 0.f, h1 = 0.f, p0 = 0.f, p1 = 0.f;
        for (int k = 0; k < KC; k++) {
            h0 += sh[k]; h1 += sh[KC + k];
            p0 += sp[k]; p1 += sp[KC + k];
        }
        out[scalar_base]     = expf(-h0) + expf(-h1);
        out[scalar_base + 1] = expf(-p0) + expf(-p1);
    }
}

// ---------------- launch --------------------------------------------------------------
extern "C" void kernel_launch(void* const* d_in, const int* in_sizes, int n_in,
                              void* d_out, int out_size) {
    const float* x     = (const float*)d_in[0];
    const float* W     = (const float*)d_in[1];
    const float* bias  = (const float*)d_in[2];
    const float* cb    = (const float*)d_in[3];
    const float* noise = (const float*)d_in[4];
    float* out = (float*)d_out;

    cudaFuncSetAttribute(gemm_hmma_kernel,
                         cudaFuncAttributeMaxDynamicSharedMemorySize, GEMM_SMEM);

    zero_kernel<<<3, 256>>>();
    dim3 wgrid(20, 24);
    wsplit_kernel<<<wgrid, 256>>>(W);
    dim3 grid(2, 256);
    gemm_hmma_kernel<<<grid, 512, GEMM_SMEM>>>(x, bias);
    epilogue_kernel<<<512, 256>>>(noise, cb, out);
    fixup_kernel<<<512, 320>>>(x, W, bias, noise, cb, out);
    finalize_kernel<<<1, GK>>>(out, out_size - 2);
}

// round 5
// speedup vs baseline: 2.8729x; 1.9640x over previous
#include <cuda_runtime.h>
#include <cuda_bf16.h>
#include <cstdint>

// ---------------------------------------------------------------------------
// GumbelVectorQuantizer on GB300 (sm_103 baseline ISA path):
//   logits = x@W + b via single-pass bf16 HMMA (approx, sigma ~0.044)
//   epilogue: gumbel argmax gather + perplexities; flags top-2 gaps < 0.6
//   fixup:    exact ascending-k FMA recompute of CANDIDATE columns only
// ---------------------------------------------------------------------------

#define BT     32768
#define DD     768
#define GK     640
#define KC     320
#define VDIM   128
#define NITER  24          // K iterations of 32
#define THETA  0.6f        // flag threshold = 2E, E = 0.3 (~6.8 sigma/logit)
#define MAXFIX 65536

__device__ float g_logits[(size_t)BT * GK];                 // 83.9 MB
__device__ float g_prob[GK];
__device__ int   g_cnt[GK];
__device__ __align__(16) __nv_bfloat16 g_wth[(size_t)GK * DD];  // W^T bf16
__device__ __align__(16) float         g_wtf[(size_t)GK * DD];  // W^T fp32
__device__ int   g_fix_cnt;
__device__ int2  g_fix[MAXFIX];

// ---------------- exact-path log (FMA pipe, ~1 ulp; round-1 validated) --------
__device__ __forceinline__ float flog(float x) {
    int xi = __float_as_int(x);
    float e = (float)(((xi >> 23) & 0xFF) - 126);
    float m = __int_as_float((xi & 0x007FFFFF) | 0x3F000000);
    if (m < 0.70710678f) { m += m; e -= 1.0f; }
    float f = m - 1.0f;
    float z = f * f;
    float p = 7.0376836292E-2f;
    p = fmaf(p, f, -1.1514610310E-1f);
    p = fmaf(p, f,  1.1676998740E-1f);
    p = fmaf(p, f, -1.2420140846E-1f);
    p = fmaf(p, f,  1.4249322787E-1f);
    p = fmaf(p, f, -1.6668057665E-1f);
    p = fmaf(p, f,  2.0000714765E-1f);
    p = fmaf(p, f, -2.4999993993E-1f);
    p = fmaf(p, f,  3.3333331174E-1f);
    float y = p * f * z;
    y = fmaf(e, -2.12194440e-4f, y);
    y = fmaf(-0.5f, z, y);
    float r = f + y;
    r = fmaf(e, 0.693359375f, r);
    return r;
}

// ---------------- PTX helpers --------------------------------------------------
__device__ __forceinline__ uint32_t smem_u32(const void* p) {
    uint32_t a;
    asm("{ .reg .u64 t; cvta.to.shared.u64 t, %1; cvt.u32.u64 %0, t; }"
        : "=r"(a) : "l"(p));
    return a;
}
#define LDMATRIX_X4(r0, r1, r2, r3, addr) \
    asm volatile("ldmatrix.sync.aligned.m8n8.x4.shared.b16 {%0,%1,%2,%3}, [%4];" \
                 : "=r"(r0), "=r"(r1), "=r"(r2), "=r"(r3) : "r"(addr))
#define MMA16816(d, a, b0, b1) \
    asm volatile("mma.sync.aligned.m16n8k16.row.col.f32.bf16.bf16.f32 " \
                 "{%0,%1,%2,%3}, {%4,%5,%6,%7}, {%8,%9}, {%0,%1,%2,%3};" \
                 : "+f"((d)[0]), "+f"((d)[1]), "+f"((d)[2]), "+f"((d)[3]) \
                 : "r"((a)[0]), "r"((a)[1]), "r"((a)[2]), "r"((a)[3]), \
                   "r"(b0), "r"(b1))
#define CP_ASYNC16(dst, src) \
    asm volatile("cp.async.cg.shared.global [%0], [%1], 16;" \
                 :: "r"(dst), "l"(src) : "memory")
#define CP_COMMIT() asm volatile("cp.async.commit_group;" ::: "memory")
#define CP_WAIT0()  asm volatile("cp.async.wait_group 0;" ::: "memory")

// smem: A[buf]: 128 rows x 80B (64B data + 16 pad); B[buf]: 320 rows x 80B
#define A_OFF(buf) ((buf) * 10240)
#define B_OFF(buf) (20480 + (buf) * 25600)
#define GEMM_SMEM 71680

__device__ __forceinline__ uint32_t pkbf(float a, float b) {
    return (uint32_t)__bfloat16_as_ushort(__float2bfloat16_rn(a)) |
           ((uint32_t)__bfloat16_as_ushort(__float2bfloat16_rn(b)) << 16);
}

// ---------------- zero ----------------------------------------------------------
__global__ void zero_kernel() {
    int t = blockIdx.x * blockDim.x + threadIdx.x;
    if (t < GK) { g_prob[t] = 0.0f; g_cnt[t] = 0; }
    if (t == GK) g_fix_cnt = 0;
}

// ---------------- W^T: bf16 + fp32, tiled transpose ------------------------------
__global__ __launch_bounds__(256)
void wsplit_kernel(const float* __restrict__ W) {
    __shared__ float tile[32][33];
    const int n0 = blockIdx.x * 32;   // 20
    const int k0 = blockIdx.y * 32;   // 24
    const int tx = threadIdx.x & 31;
    const int ty = threadIdx.x >> 5;
#pragma unroll
    for (int i = 0; i < 32; i += 8)
        tile[ty + i][tx] = W[(size_t)(k0 + ty + i) * GK + n0 + tx];
    __syncthreads();
#pragma unroll
    for (int i = 0; i < 32; i += 8) {
        const int n = n0 + ty + i, k = k0 + tx;
        float x = tile[tx][ty + i];
        g_wth[(size_t)n * DD + k] = __float2bfloat16_rn(x);
        g_wtf[(size_t)n * DD + k] = x;
    }
}

// ---------------- HMMA GEMM (single bf16 pass, KTILE=32) --------------------------
__global__ __launch_bounds__(512, 1)
void gemm_hmma_kernel(const float* __restrict__ X, const float* __restrict__ bias) {
    extern __shared__ char sm[];
    const uint32_t smb = smem_u32(sm);
    const int tid  = threadIdx.x;
    const int lane = tid & 31;
    const int wid  = tid >> 5;
    const int wm   = wid & 3;
    const int wn   = wid >> 2;
    const int g    = blockIdx.x;
    const int bm   = blockIdx.y;

    float acc[2][10][4];
#pragma unroll
    for (int i = 0; i < 2; i++)
#pragma unroll
        for (int j = 0; j < 10; j++)
#pragma unroll
            for (int q = 0; q < 4; q++) acc[i][j][q] = 0.0f;

    const int a_row = tid >> 2;
    const int a_q   = tid & 3;
    const float* Xrow = X + (size_t)(bm * 128 + a_row) * DD + a_q * 8;

    // prologue: iter 0
    for (int idx = tid; idx < 1280; idx += 512) {
        int n = idx >> 2, c = idx & 3;
        CP_ASYNC16(smb + B_OFF(0) + n * 80 + c * 16,
                   &g_wth[(size_t)(g * KC + n) * DD + c * 8]);
    }
    CP_COMMIT();
    {
        float4 v0 = *(const float4*)(Xrow);
        float4 v1 = *(const float4*)(Xrow + 4);
        uint4 pk = make_uint4(pkbf(v0.x, v0.y), pkbf(v0.z, v0.w),
                              pkbf(v1.x, v1.y), pkbf(v1.z, v1.w));
        *(uint4*)(sm + A_OFF(0) + a_row * 80 + a_q * 16) = pk;
    }
    CP_WAIT0();
    __syncthreads();

    const int a_lrow = (lane & 15);
    const int a_lcol = (lane >> 4) * 16;
    const int b_lrow = (lane & 7) + ((lane >> 4) & 1) * 8;
    const int b_lcol = ((lane >> 3) & 1) * 16;
    const int b_nbase = (wn * 80 + b_lrow) * 80 + b_lcol;

    int buf = 0;
    for (int t = 0; t < NITER; t++) {
        float4 nv0, nv1;
        if (t + 1 < NITER) {
            nv0 = *(const float4*)(Xrow + (t + 1) * 32);
            nv1 = *(const float4*)(Xrow + (t + 1) * 32 + 4);
            const int k0 = (t + 1) * 32;
            for (int idx = tid; idx < 1280; idx += 512) {
                int n = idx >> 2, c = idx & 3;
                CP_ASYNC16(smb + B_OFF(buf ^ 1) + n * 80 + c * 16,
                           &g_wth[(size_t)(g * KC + n) * DD + k0 + c * 8]);
            }
            CP_COMMIT();
        }

        // ---- compute: 2 k16 halves ----
#pragma unroll
        for (int kh = 0; kh < 2; kh++) {
            uint32_t ah[2][4];
#pragma unroll
            for (int mt = 0; mt < 2; mt++) {
                const int row = wm * 32 + mt * 16 + a_lrow;
                LDMATRIX_X4(ah[mt][0], ah[mt][1], ah[mt][2], ah[mt][3],
                            smb + A_OFF(buf) + row * 80 + kh * 32 + a_lcol);
            }
            uint32_t bb[2][4];
            LDMATRIX_X4(bb[0][0], bb[0][1], bb[0][2], bb[0][3],
                        smb + B_OFF(buf) + b_nbase + kh * 32);
#pragma unroll
            for (int bg = 0; bg < 5; bg++) {
                const int cur = bg & 1, nxt = cur ^ 1;
                if (bg < 4)
                    LDMATRIX_X4(bb[nxt][0], bb[nxt][1], bb[nxt][2], bb[nxt][3],
                                smb + B_OFF(buf) + b_nbase + (bg + 1) * 16 * 80 + kh * 32);
#pragma unroll
                for (int h2 = 0; h2 < 2; h2++) {
                    MMA16816(acc[0][bg * 2 + h2], ah[0], bb[cur][h2 * 2], bb[cur][h2 * 2 + 1]);
                    MMA16816(acc[1][bg * 2 + h2], ah[1], bb[cur][h2 * 2], bb[cur][h2 * 2 + 1]);
                }
            }
        }

        if (t + 1 < NITER) {
            uint4 pk = make_uint4(pkbf(nv0.x, nv0.y), pkbf(nv0.z, nv0.w),
                                  pkbf(nv1.x, nv1.y), pkbf(nv1.z, nv1.w));
            *(uint4*)(sm + A_OFF(buf ^ 1) + a_row * 80 + a_q * 16) = pk;
            CP_WAIT0();
        }
        __syncthreads();
        buf ^= 1;
    }

    // ---- store D + bias -> g_logits ----
#pragma unroll
    for (int nt = 0; nt < 10; nt++) {
        const int c = wn * 80 + nt * 8 + (lane & 3) * 2;
        const float b0 = bias[g * KC + c];
        const float b1 = bias[g * KC + c + 1];
#pragma unroll
        for (int mt = 0; mt < 2; mt++) {
            const int r0 = bm * 128 + wm * 32 + mt * 16 + (lane >> 2);
            float* p0 = g_logits + ((size_t)r0 * 2 + g) * KC + c;
            float* p1 = g_logits + ((size_t)(r0 + 8) * 2 + g) * KC + c;
            *(float2*)p0 = make_float2(acc[mt][nt][0] + b0, acc[mt][nt][1] + b1);
            *(float2*)p1 = make_float2(acc[mt][nt][2] + b0, acc[mt][nt][3] + b1);
        }
    }
}

// ---------------- fused epilogue ------------------------------------------------
__global__ __launch_bounds__(256)
void epilogue_kernel(const float* __restrict__ noise,
                     const float* __restrict__ cb,
                     float* __restrict__ out) {
    __shared__ float s_prob[GK];
    __shared__ int   s_cnt[GK];
    const int tid = threadIdx.x;
    for (int i = tid; i < GK; i += 256) { s_prob[i] = 0.0f; s_cnt[i] = 0; }
    __syncthreads();

    const int lane = tid & 31;
    const int warp = tid >> 5;
    const int pair0 = (blockIdx.x * 8 + warp) * 16;

    float pacc[2][10];
#pragma unroll
    for (int g2 = 0; g2 < 2; g2++)
#pragma unroll
        for (int j = 0; j < 10; j++) pacc[g2][j] = 0.0f;

    for (int pp = 0; pp < 16; pp++) {
        const int pair = pair0 + pp;
        const int r = pair >> 1;
        const int g = pair & 1;
        const float* lrow = g_logits + (size_t)pair * KC;
        const float* nrow = noise    + (size_t)pair * KC;

        float l[10], gl[10];
#pragma unroll
        for (int j = 0; j < 10; j++) {
            const int k = lane + 32 * j;
            const float lv = lrow[k];
            float u = nrow[k];
            u = fmaf(u, 0.999998f, 1e-6f);
            float nlu = -__logf(u);
            if (u > 0.99f) nlu = -flog(u);     // guard: __logf abs-err near 1
            const float gum = -__logf(nlu);
            l[j]  = lv;
            gl[j] = lv + gum;
        }

        // hard top-2
        float M = l[0], M2 = -3.4e38f; int I = lane;
#pragma unroll
        for (int j = 1; j < 10; j++) {
            if (l[j] > M) { M2 = M; M = l[j]; I = lane + 32 * j; }
            else if (l[j] > M2) M2 = l[j];
        }
#pragma unroll
        for (int off = 16; off; off >>= 1) {
            float ov = __shfl_down_sync(0xffffffffu, M, off);
            int   oi = __shfl_down_sync(0xffffffffu, I, off);
            float o2 = __shfl_down_sync(0xffffffffu, M2, off);
            if (ov > M || (ov == M && oi < I)) { M2 = fmaxf(M, o2); M = ov; I = oi; }
            else                                { M2 = fmaxf(M2, ov); }
        }
        M  = __shfl_sync(0xffffffffu, M, 0);
        M2 = __shfl_sync(0xffffffffu, M2, 0);
        I  = __shfl_sync(0xffffffffu, I, 0);

        // gumbel top-2
        float GM = gl[0], GM2 = -3.4e38f; int GI = lane;
#pragma unroll
        for (int j = 1; j < 10; j++) {
            if (gl[j] > GM) { GM2 = GM; GM = gl[j]; GI = lane + 32 * j; }
            else if (gl[j] > GM2) GM2 = gl[j];
        }
#pragma unroll
        for (int off = 16; off; off >>= 1) {
            float ov = __shfl_down_sync(0xffffffffu, GM, off);
            int   oi = __shfl_down_sync(0xffffffffu, GI, off);
            float o2 = __shfl_down_sync(0xffffffffu, GM2, off);
            if (ov > GM || (ov == GM && oi < GI)) { GM2 = fmaxf(GM, o2); GM = ov; GI = oi; }
            else                                   { GM2 = fmaxf(GM2, ov); }
        }
        GM  = __shfl_sync(0xffffffffu, GM, 0);
        GM2 = __shfl_sync(0xffffffffu, GM2, 0);
        GI  = __shfl_sync(0xffffffffu, GI, 0);

        // softmax accumulation
        float e[10];
        float s = 0.0f;
#pragma unroll
        for (int j = 0; j < 10; j++) { e[j] = __expf(l[j] - M); s += e[j]; }
#pragma unroll
        for (int off = 16; off; off >>= 1)
            s += __shfl_xor_sync(0xffffffffu, s, off);
        const float inv = 1.0f / s;
#pragma unroll
        for (int j = 0; j < 10; j++) pacc[g][j] += e[j] * inv;

        if (lane == 0) {
            atomicAdd(&s_cnt[g * KC + I], 1);
            if (M - M2 < THETA || GM - GM2 < THETA) {
                int pos = atomicAdd(&g_fix_cnt, 1);
                if (pos < MAXFIX) g_fix[pos] = make_int2(pair, I);
            }
        }

        const float4* src = (const float4*)(cb + ((size_t)(g * KC) + GI) * VDIM);
        float4*       dst = (float4*)(out + (size_t)r * 256 + g * VDIM);
        dst[lane] = src[lane];
    }

#pragma unroll
    for (int g2 = 0; g2 < 2; g2++)
#pragma unroll
        for (int j = 0; j < 10; j++)
            atomicAdd(&s_prob[g2 * KC + lane + 32 * j], pacc[g2][j]);

    __syncthreads();
    for (int i = tid; i < GK; i += 256) {
        atomicAdd(&g_prob[i], s_prob[i]);
        atomicAdd(&g_cnt[i],  s_cnt[i]);
    }
}

// ---------------- fixup: exact resolve of candidate columns ----------------------
// One warp per flagged pair. Candidates = cols within THETA of approx top
// (hard and/or gumbel). Exact ascending-k FMA chain per candidate (1 lane each).
__global__ __launch_bounds__(256)
void fixup_kernel(const float* __restrict__ X, const float* __restrict__ bias,
                  const float* __restrict__ noise, const float* __restrict__ cb,
                  float* __restrict__ out) {
    __shared__ int s_cols[8][32];
    __shared__ int s_n[8];
    const int lane = threadIdx.x & 31;
    const int w    = threadIdx.x >> 5;
    const int gw   = blockIdx.x * 8 + w;
    const int nwarps = gridDim.x * 8;
    const int total = min(g_fix_cnt, MAXFIX);

    for (int f = gw; f < total; f += nwarps) {
        const int2 rec = g_fix[f];
        const int pair = rec.x, Iapp = rec.y;
        const int r = pair >> 1, g = pair & 1;
        const float* lrow = g_logits + (size_t)pair * KC;
        const float* nrow = noise    + (size_t)pair * KC;

        float l[10], gl[10];
#pragma unroll
        for (int j = 0; j < 10; j++) {
            const int k = lane + 32 * j;
            l[j] = lrow[k];
            float u = fmaf(nrow[k], 0.999998f, 1e-6f);
            gl[j] = l[j] - flog(-flog(u));       // exact-path gumbel
        }
        // approx tops (values only)
        float M = l[0], GM = gl[0];
#pragma unroll
        for (int j = 1; j < 10; j++) { M = fmaxf(M, l[j]); GM = fmaxf(GM, gl[j]); }
#pragma unroll
        for (int off = 16; off; off >>= 1) {
            M  = fmaxf(M,  __shfl_xor_sync(0xffffffffu, M,  off));
            GM = fmaxf(GM, __shfl_xor_sync(0xffffffffu, GM, off));
        }

        if (lane == 0) s_n[w] = 0;
        __syncwarp();
#pragma unroll
        for (int j = 0; j < 10; j++) {
            const int hardc = l[j]  > M  - THETA;
            const int gumc  = gl[j] > GM - THETA;
            if (hardc || gumc) {
                int p = atomicAdd(&s_n[w], 1);
                if (p < 32)
                    s_cols[w][p] = (lane + 32 * j) | (hardc << 16) | (gumc << 17);
            }
        }
        __syncwarp();
        const int cnt = min(s_n[w], 32);

        // exact recompute per candidate (one lane each)
        float le = -3.4e38f, ge = -3.4e38f;
        int ci = KC;
        if (lane < cnt) {
            const int ent = s_cols[w][lane];
            ci = ent & 0xFFFF;
            const float* xr = X + (size_t)r * DD;
            const float* wc = g_wtf + (size_t)(g * KC + ci) * DD;
            float acc = 0.0f;
            for (int k = 0; k < DD; k++)
                acc = fmaf(xr[k], wc[k], acc);       // ascending-k exact chain
            const float ex = acc + bias[g * KC + ci];
            float u = fmaf(nrow[ci], 0.999998f, 1e-6f);
            const float gum = -flog(-flog(u));
            if (ent & 0x10000) le = ex;
            if (ent & 0x20000) ge = ex + gum;
        }
        // warp argmax (tie -> smaller col)
        int hi = ci, gi = ci;
        float hv = le, gv = ge;
#pragma unroll
        for (int off = 16; off; off >>= 1) {
            float ov = __shfl_xor_sync(0xffffffffu, hv, off);
            int   oi = __shfl_xor_sync(0xffffffffu, hi, off);
            if (ov > hv || (ov == hv && oi < hi)) { hv = ov; hi = oi; }
            float o2 = __shfl_xor_sync(0xffffffffu, gv, off);
            int   i2 = __shfl_xor_sync(0xffffffffu, gi, off);
            if (o2 > gv || (o2 == gv && i2 < gi)) { gv = o2; gi = i2; }
        }

        if (lane == 0 && hi != Iapp) {
            atomicSub(&g_cnt[g * KC + Iapp], 1);
            atomicAdd(&g_cnt[g * KC + hi], 1);
        }
        // rewrite output row with exact gumbel winner
        const float4* src = (const float4*)(cb + ((size_t)(g * KC) + gi) * VDIM);
        float4*       dst = (float4*)(out + (size_t)r * 256 + g * VDIM);
        dst[lane] = src[lane];
        __syncwarp();
    }
}

// ---------------- perplexity scalars -----------------------------------------------
__global__ void finalize_kernel(float* __restrict__ out, int scalar_base) {
    __shared__ float sh[GK], sp[GK];
    const int t = threadIdx.x;
    if (t < GK) {
        float hp = (float)g_cnt[t] * (1.0f / (float)BT);
        float ap = g_prob[t]       * (1.0f / (float)BT);
        sh[t] = hp * logf(hp + 1e-7f);
        sp[t] = ap * logf(ap + 1e-7f);
    }
    __syncthreads();
    if (t == 0) {
        float h0 = 0.f, h1 = 0.f, p0 = 0.f, p1 = 0.f;
        for (int k = 0; k < KC; k++) {
            h0 += sh[k]; h1 += sh[KC + k];
            p0 += sp[k]; p1 += sp[KC + k];
        }
        out[scalar_base]     = expf(-h0) + expf(-h1);
        out[scalar_base + 1] = expf(-p0) + expf(-p1);
    }
}

// ---------------- launch --------------------------------------------------------------
extern "C" void kernel_launch(void* const* d_in, const int* in_sizes, int n_in,
                              void* d_out, int out_size) {
    const float* x     = (const float*)d_in[0];
    const float* W     = (const float*)d_in[1];
    const float* bias  = (const float*)d_in[2];
    const float* cb    = (const float*)d_in[3];
    const float* noise = (const float*)d_in[4];
    float* out = (float*)d_out;

    cudaFuncSetAttribute(gemm_hmma_kernel,
                         cudaFuncAttributeMaxDynamicSharedMemorySize, GEMM_SMEM);

    zero_kernel<<<3, 256>>>();
    dim3 wgrid(20, 24);
    wsplit_kernel<<<wgrid, 256>>>(W);
    dim3 grid(2, 256);
    gemm_hmma_kernel<<<grid, 512, GEMM_SMEM>>>(x, bias);
    epilogue_kernel<<<512, 256>>>(noise, cb, out);
    fixup_kernel<<<512, 256>>>(x, bias, noise, cb, out);
    finalize_kernel<<<1, GK>>>(out, out_size - 2);
}